// round 13
// baseline (speedup 1.0000x reference)
#include <cuda_runtime.h>

#define N_DIM 8192
#define ROW4 (N_DIM / 4)          // 2048 float4 per row
#define TOTAL4 (N_DIM * ROW4)     // 16,777,216 float4 elements
#define HALF4 (TOTAL4 / 2)        // 8,388,608
#define GRID 2048
#define TPB 256
#define NITER 16                  // HALF4 / (GRID*TPB) exactly

// Global accumulators + ticket. Statically zero on first call; the last block
// resets them after consuming, so every launch/replay starts from zero.
__device__ double   g_sumAbsC = 0.0;
__device__ double   g_sumCW   = 0.0;
__device__ double   g_sumW    = 0.0;
__device__ unsigned g_ticket  = 0;

__global__ __launch_bounds__(TPB) void parietal_fused_kernel(
    const float*  __restrict__ a,       // [N_DIM] neural activities
    const float4* __restrict__ W4,      // [N*N/4] connection matrix
    const float4* __restrict__ Cin4,    // [N*N/4] correlation matrix (in)
    float4*       __restrict__ Cout4,   // [N*N/4] C (out)
    const float*  __restrict__ coh_in,  // [1] coherence_strength
    const float*  __restrict__ integ_in,// [1] integration_measure
    float*        __restrict__ out_tail)// d_out + N*N (3 floats)
{
    const float decay = 0.9f;
    const float one_minus = 0.1f;
    const int stride = GRID * TPB;

    float sAbs = 0.0f, sCW = 0.0f, sW = 0.0f;

    int idx = blockIdx.x * TPB + threadIdx.x;

    // Pipeline prologue: loads for iteration 0.
    float4 c0 = Cin4[idx];
    float4 w0 = W4[idx];
    float4 c1 = Cin4[idx + HALF4];
    float4 w1 = W4[idx + HALF4];

    #pragma unroll 1
    for (int it = 0; it < NITER; ++it) {
        const int nextIdx = idx + stride;

        // Prefetch iteration it+1 (predicated off on the last iteration).
        float4 nc0, nw0, nc1, nw1;
        if (it < NITER - 1) {
            nc0 = Cin4[nextIdx];
            nw0 = W4[nextIdx];
            nc1 = Cin4[nextIdx + HALF4];
            nw1 = W4[nextIdx + HALF4];
        }

        // --- element A (idx) ---
        {
            const int i  = idx >> 11;
            const int j4 = idx & 2047;
            const float  ai = __ldg(&a[i]);
            const float4 aj = reinterpret_cast<const float4*>(a)[j4];
            const int diagLane = ((i >> 2) == j4) ? (i & 3) : -1;

            float o0 = (diagLane == 0) ? c0.x : fmaf(one_minus * ai, aj.x, decay * c0.x);
            float o1 = (diagLane == 1) ? c0.y : fmaf(one_minus * ai, aj.y, decay * c0.y);
            float o2 = (diagLane == 2) ? c0.z : fmaf(one_minus * ai, aj.z, decay * c0.z);
            float o3 = (diagLane == 3) ? c0.w : fmaf(one_minus * ai, aj.w, decay * c0.w);

            const float a0 = fabsf(o0), a1 = fabsf(o1), a2 = fabsf(o2), a3 = fabsf(o3);
            sAbs += (a0 + a1) + (a2 + a3);
            sW   += (w0.x + w0.y) + (w0.z + w0.w);
            sCW  += (a0 * w0.x + a1 * w0.y) + (a2 * w0.z + a3 * w0.w);

            Cout4[idx] = make_float4(o0, o1, o2, o3);
        }

        // --- element B (idx + HALF4) ---
        {
            const int idxB = idx + HALF4;
            const int i  = idxB >> 11;
            const int j4 = idxB & 2047;
            const float  ai = __ldg(&a[i]);
            const float4 aj = reinterpret_cast<const float4*>(a)[j4];
            const int diagLane = ((i >> 2) == j4) ? (i & 3) : -1;

            float o0 = (diagLane == 0) ? c1.x : fmaf(one_minus * ai, aj.x, decay * c1.x);
            float o1 = (diagLane == 1) ? c1.y : fmaf(one_minus * ai, aj.y, decay * c1.y);
            float o2 = (diagLane == 2) ? c1.z : fmaf(one_minus * ai, aj.z, decay * c1.z);
            float o3 = (diagLane == 3) ? c1.w : fmaf(one_minus * ai, aj.w, decay * c1.w);

            const float a0 = fabsf(o0), a1 = fabsf(o1), a2 = fabsf(o2), a3 = fabsf(o3);
            sAbs += (a0 + a1) + (a2 + a3);
            sW   += (w1.x + w1.y) + (w1.z + w1.w);
            sCW  += (a0 * w1.x + a1 * w1.y) + (a2 * w1.z + a3 * w1.w);

            Cout4[idxB] = make_float4(o0, o1, o2, o3);
        }

        // Rotate pipeline registers.
        idx = nextIdx;
        c0 = nc0; w0 = nw0; c1 = nc1; w1 = nw1;
    }

    // ---- block reduction (warp shuffle + smem) ----
    #pragma unroll
    for (int off = 16; off > 0; off >>= 1) {
        sAbs += __shfl_down_sync(0xFFFFFFFFu, sAbs, off);
        sCW  += __shfl_down_sync(0xFFFFFFFFu, sCW,  off);
        sW   += __shfl_down_sync(0xFFFFFFFFu, sW,   off);
    }

    __shared__ float redAbs[8], redCW[8], redW[8];
    const int lane = threadIdx.x & 31;
    const int wid  = threadIdx.x >> 5;
    if (lane == 0) { redAbs[wid] = sAbs; redCW[wid] = sCW; redW[wid] = sW; }
    __syncthreads();

    if (threadIdx.x == 0) {
        float bAbs = 0.0f, bCW = 0.0f, bW = 0.0f;
        #pragma unroll
        for (int k = 0; k < TPB / 32; k++) {
            bAbs += redAbs[k]; bCW += redCW[k]; bW += redW[k];
        }
        // Sum atomics: L2-resident RMWs (no L1 involvement).
        atomicAdd(&g_sumAbsC, (double)bAbs);
        atomicAdd(&g_sumCW,   (double)bCW);
        atomicAdd(&g_sumW,    (double)bW);

        // Release-ticket: orders the three atomicAdds above before the ticket
        // becomes visible, WITHOUT a gpu-scope membar (no CCTL.IVALL L1 flush).
        unsigned t;
        asm volatile("atom.release.gpu.global.add.u32 %0, [%1], %2;"
                     : "=r"(t)
                     : "l"(&g_ticket), "r"(1u)
                     : "memory");

        if (t == GRID - 1) {
            // All blocks' sum atomics have performed at L2 (release chain).
            const double corr_sum = atomicAdd(&g_sumAbsC, 0.0);
            const double cw_sum   = atomicAdd(&g_sumCW,   0.0);
            const double w_sum    = atomicAdd(&g_sumW,    0.0);

            const double n_conn = (double)N_DIM * (double)(N_DIM - 1);
            float coherence = 0.9f * coh_in[0] + 0.1f * (float)(corr_sum / n_conn);

            float integration;
            if (w_sum > 0.0) {
                integration = 0.9f * integ_in[0] + 0.1f * (float)(cw_sum / w_sum);
            } else {
                integration = integ_in[0];
            }

            const double n_total = (double)N_DIM * (double)N_DIM;
            float synchrony = (float)(corr_sum / n_total);

            out_tail[0] = coherence;
            out_tail[1] = integration;
            out_tail[2] = synchrony;

            // Reset state for the next launch / graph replay (deterministic).
            g_sumAbsC = 0.0;
            g_sumCW   = 0.0;
            g_sumW    = 0.0;
            g_ticket  = 0;
        }
    }
}

extern "C" void kernel_launch(void* const* d_in, const int* in_sizes, int n_in,
                              void* d_out, int out_size) {
    const float* a     = (const float*)d_in[0];   // neural_activities [8192]
    const float* W     = (const float*)d_in[1];   // connection_matrix [8192*8192]
    const float* Cin   = (const float*)d_in[2];   // correlation_matrix [8192*8192]
    const float* coh   = (const float*)d_in[3];   // coherence_strength [1]
    const float* integ = (const float*)d_in[4];   // integration_measure [1]

    float* out = (float*)d_out;   // [N*N] C, then coherence, integration, synchrony

    parietal_fused_kernel<<<GRID, TPB>>>(
        a,
        (const float4*)W,
        (const float4*)Cin,
        (float4*)out,
        coh, integ,
        out + (size_t)N_DIM * N_DIM);
}

// round 15
// speedup vs baseline: 1.0338x; 1.0338x over previous
#include <cuda_runtime.h>

#define N_DIM 8192
#define ROW4 (N_DIM / 4)          // 2048 float4 per row
#define TOTAL4 (N_DIM * ROW4)     // 16,777,216 float4 elements
#define HALF4 (TOTAL4 / 2)        // 8,388,608
#define GRID 2048
#define TPB 256

// Global accumulators + ticket. Statically zero on first call; the last block
// resets them after consuming, so every launch/replay starts from zero.
__device__ double   g_sumAbsC = 0.0;
__device__ double   g_sumCW   = 0.0;
__device__ double   g_sumW    = 0.0;
__device__ unsigned g_ticket  = 0;

__global__ __launch_bounds__(TPB) void parietal_fused_kernel(
    const float*  __restrict__ a,       // [N_DIM] neural activities
    const float4* __restrict__ W4,      // [N*N/4] connection matrix
    const float4* __restrict__ Cin4,    // [N*N/4] correlation matrix (in)
    float4*       __restrict__ Cout4,   // [N*N/4] C (out)
    const float*  __restrict__ coh_in,  // [1] coherence_strength
    const float*  __restrict__ integ_in,// [1] integration_measure
    float*        __restrict__ out_tail)// d_out + N*N (3 floats)
{
    const float decay = 0.9f;
    const float one_minus = 0.1f;

    float sAbs = 0.0f, sCW = 0.0f, sW = 0.0f;

    const int stride = GRID * TPB;
    for (int idx = blockIdx.x * TPB + threadIdx.x; idx < HALF4; idx += stride) {
        const int idxB = idx + HALF4;

        // 4 independent 16B global loads in flight (MLP sweet spot per R5-R13).
        const float4 c0 = Cin4[idx];
        const float4 w0 = W4[idx];
        const float4 c1 = Cin4[idxB];
        const float4 w1 = W4[idxB];

        // --- element A ---
        {
            const int i  = idx >> 11;
            const int j4 = idx & 2047;
            const float  ai = __ldg(&a[i]);
            const float4 aj = reinterpret_cast<const float4*>(a)[j4];
            const int diagLane = ((i >> 2) == j4) ? (i & 3) : -1;

            float o0 = (diagLane == 0) ? c0.x : fmaf(one_minus * ai, aj.x, decay * c0.x);
            float o1 = (diagLane == 1) ? c0.y : fmaf(one_minus * ai, aj.y, decay * c0.y);
            float o2 = (diagLane == 2) ? c0.z : fmaf(one_minus * ai, aj.z, decay * c0.z);
            float o3 = (diagLane == 3) ? c0.w : fmaf(one_minus * ai, aj.w, decay * c0.w);

            const float a0 = fabsf(o0), a1 = fabsf(o1), a2 = fabsf(o2), a3 = fabsf(o3);
            sAbs += (a0 + a1) + (a2 + a3);
            sW   += (w0.x + w0.y) + (w0.z + w0.w);
            sCW  += (a0 * w0.x + a1 * w0.y) + (a2 * w0.z + a3 * w0.w);

            Cout4[idx] = make_float4(o0, o1, o2, o3);
        }

        // --- element B ---
        {
            const int i  = idxB >> 11;
            const int j4 = idxB & 2047;
            const float  ai = __ldg(&a[i]);
            const float4 aj = reinterpret_cast<const float4*>(a)[j4];
            const int diagLane = ((i >> 2) == j4) ? (i & 3) : -1;

            float o0 = (diagLane == 0) ? c1.x : fmaf(one_minus * ai, aj.x, decay * c1.x);
            float o1 = (diagLane == 1) ? c1.y : fmaf(one_minus * ai, aj.y, decay * c1.y);
            float o2 = (diagLane == 2) ? c1.z : fmaf(one_minus * ai, aj.z, decay * c1.z);
            float o3 = (diagLane == 3) ? c1.w : fmaf(one_minus * ai, aj.w, decay * c1.w);

            const float a0 = fabsf(o0), a1 = fabsf(o1), a2 = fabsf(o2), a3 = fabsf(o3);
            sAbs += (a0 + a1) + (a2 + a3);
            sW   += (w1.x + w1.y) + (w1.z + w1.w);
            sCW  += (a0 * w1.x + a1 * w1.y) + (a2 * w1.z + a3 * w1.w);

            Cout4[idxB] = make_float4(o0, o1, o2, o3);
        }
    }

    // ---- block reduction (warp shuffle + smem) ----
    #pragma unroll
    for (int off = 16; off > 0; off >>= 1) {
        sAbs += __shfl_down_sync(0xFFFFFFFFu, sAbs, off);
        sCW  += __shfl_down_sync(0xFFFFFFFFu, sCW,  off);
        sW   += __shfl_down_sync(0xFFFFFFFFu, sW,   off);
    }

    __shared__ float redAbs[8], redCW[8], redW[8];
    const int lane = threadIdx.x & 31;
    const int wid  = threadIdx.x >> 5;
    if (lane == 0) { redAbs[wid] = sAbs; redCW[wid] = sCW; redW[wid] = sW; }
    __syncthreads();

    if (threadIdx.x == 0) {
        float bAbs = 0.0f, bCW = 0.0f, bW = 0.0f;
        #pragma unroll
        for (int k = 0; k < TPB / 32; k++) {
            bAbs += redAbs[k]; bCW += redCW[k]; bW += redW[k];
        }
        // Sum atomics: L2-resident RMWs (no L1 involvement).
        atomicAdd(&g_sumAbsC, (double)bAbs);
        atomicAdd(&g_sumCW,   (double)bCW);
        atomicAdd(&g_sumW,    (double)bW);

        // Release-ticket: orders the three atomicAdds above before the ticket
        // becomes visible, WITHOUT a gpu-scope membar (no CCTL.IVALL L1 flush).
        unsigned t;
        asm volatile("atom.release.gpu.global.add.u32 %0, [%1], %2;"
                     : "=r"(t)
                     : "l"(&g_ticket), "r"(1u)
                     : "memory");

        if (t == GRID - 1) {
            // All blocks' sum atomics have performed at L2 (release chain).
            const double corr_sum = atomicAdd(&g_sumAbsC, 0.0);
            const double cw_sum   = atomicAdd(&g_sumCW,   0.0);
            const double w_sum    = atomicAdd(&g_sumW,    0.0);

            const double n_conn = (double)N_DIM * (double)(N_DIM - 1);
            float coherence = 0.9f * coh_in[0] + 0.1f * (float)(corr_sum / n_conn);

            float integration;
            if (w_sum > 0.0) {
                integration = 0.9f * integ_in[0] + 0.1f * (float)(cw_sum / w_sum);
            } else {
                integration = integ_in[0];
            }

            const double n_total = (double)N_DIM * (double)N_DIM;
            float synchrony = (float)(corr_sum / n_total);

            out_tail[0] = coherence;
            out_tail[1] = integration;
            out_tail[2] = synchrony;

            // Reset state for the next launch / graph replay (deterministic).
            g_sumAbsC = 0.0;
            g_sumCW   = 0.0;
            g_sumW    = 0.0;
            g_ticket  = 0;
        }
    }
}

extern "C" void kernel_launch(void* const* d_in, const int* in_sizes, int n_in,
                              void* d_out, int out_size) {
    const float* a     = (const float*)d_in[0];   // neural_activities [8192]
    const float* W     = (const float*)d_in[1];   // connection_matrix [8192*8192]
    const float* Cin   = (const float*)d_in[2];   // correlation_matrix [8192*8192]
    const float* coh   = (const float*)d_in[3];   // coherence_strength [1]
    const float* integ = (const float*)d_in[4];   // integration_measure [1]

    float* out = (float*)d_out;   // [N*N] C, then coherence, integration, synchrony

    parietal_fused_kernel<<<GRID, TPB>>>(
        a,
        (const float4*)W,
        (const float4*)Cin,
        (float4*)out,
        coh, integ,
        out + (size_t)N_DIM * N_DIM);
}